// round 3
// baseline (speedup 1.0000x reference)
#include <cuda_runtime.h>
#include <cuda_bf16.h>
#include <math.h>

#define NMAX 100000
#define EMAX 1600000
#define D    128
#define D4   32
#define NG   64
#define NEG_SLOPE 0.2f

// ---------------- scratch (static device globals; no allocs allowed) ----------------
__device__ float g_feat[NMAX * D];     // x @ W for current layer
__device__ float g_x[NMAX * D];        // layer output / next layer input
__device__ float g_el[NMAX];
__device__ float g_er[NMAX];
__device__ int   g_counts[NMAX];
__device__ int   g_offsets[NMAX + 1];
__device__ int   g_cursor[NMAX];
__device__ int   g_esrc[EMAX];         // src node of each edge, sorted by dst
__device__ float g_hg[NG * D];
__device__ int   g_gcnt[NG];

// ---------------- zeroing ----------------
__global__ void zero_kernel(int n_nodes) {
    int i = blockIdx.x * blockDim.x + threadIdx.x;
    int stride = gridDim.x * blockDim.x;
    for (int k = i; k < n_nodes; k += stride) g_counts[k] = 0;
    for (int k = i; k < NG * D; k += stride) g_hg[k] = 0.0f;
}

// ---------------- CSR build ----------------
__global__ void hist_kernel(const int* __restrict__ dst, int E) {
    int i = blockIdx.x * blockDim.x + threadIdx.x;
    int stride = gridDim.x * blockDim.x;
    for (int e = i; e < E; e += stride) atomicAdd(&g_counts[dst[e]], 1);
}

__global__ void scan_kernel(int n_nodes) {
    __shared__ int sums[1024];
    int t = threadIdx.x;
    int chunk = (n_nodes + 1023) / 1024;
    int begin = t * chunk;
    int end = begin + chunk; if (end > n_nodes) end = n_nodes;
    int s = 0;
    for (int i = begin; i < end && i < n_nodes; i++) s += g_counts[i];
    sums[t] = s;
    __syncthreads();
    // Hillis-Steele inclusive scan
    for (int off = 1; off < 1024; off <<= 1) {
        int v = (t >= off) ? sums[t - off] : 0;
        __syncthreads();
        sums[t] += v;
        __syncthreads();
    }
    int run = (t > 0) ? sums[t - 1] : 0;
    for (int i = begin; i < end && i < n_nodes; i++) {
        int c = g_counts[i];
        g_offsets[i] = run;
        g_cursor[i]  = run;
        run += c;
    }
    if (t == 1023) g_offsets[n_nodes] = sums[1023];
}

__global__ void scatter_kernel(const int* __restrict__ src, const int* __restrict__ dst, int E) {
    int i = blockIdx.x * blockDim.x + threadIdx.x;
    int stride = gridDim.x * blockDim.x;
    for (int e = i; e < E; e += stride) {
        int d = dst[e];
        int pos = atomicAdd(&g_cursor[d], 1);
        g_esrc[pos] = src[e];
    }
}

// ---------------- GEMM: out[N,128] = X[N,128] @ W[128,128] ----------------
// 256 threads/block, 64-row tile, W fully staged in SMEM, 4x8 register tiles.
__global__ void gemm_kernel(const float* __restrict__ X, const float* __restrict__ W,
                            float* __restrict__ out, int n_rows) {
    extern __shared__ float sm[];
    float* Ws = sm;            // 128*128 floats = 64KB
    float* Xs = sm + D * D;    // 64*128 floats  = 32KB
    int tid = threadIdx.x;
    int row0 = blockIdx.x * 64;

    // stage W (64 float4 per thread? -> 128*128/4 = 4096 float4 / 256 = 16 each)
    for (int i = tid; i < (D * D) / 4; i += 256)
        ((float4*)Ws)[i] = ((const float4*)W)[i];
    // stage X tile: 64*128/4 = 2048 float4
    for (int i = tid; i < (64 * D) / 4; i += 256) {
        int r = i / D4;
        int c = i % D4;
        int gr = row0 + r;
        float4 v = make_float4(0.f, 0.f, 0.f, 0.f);
        if (gr < n_rows) v = ((const float4*)X)[gr * D4 + c];
        ((float4*)Xs)[i] = v;
    }
    __syncthreads();

    int tx = tid & 15;        // 16 col groups of 8
    int ty = tid >> 4;        // 16 row groups of 4
    int c0 = tx * 8;
    float acc[4][8];
#pragma unroll
    for (int r = 0; r < 4; r++)
#pragma unroll
        for (int c = 0; c < 8; c++) acc[r][c] = 0.f;

#pragma unroll 4
    for (int k = 0; k < D; k++) {
        float a0 = Xs[(ty * 4 + 0) * D + k];
        float a1 = Xs[(ty * 4 + 1) * D + k];
        float a2 = Xs[(ty * 4 + 2) * D + k];
        float a3 = Xs[(ty * 4 + 3) * D + k];
        float4 b0 = *(float4*)&Ws[k * D + c0];
        float4 b1 = *(float4*)&Ws[k * D + c0 + 4];
        float bb[8] = {b0.x, b0.y, b0.z, b0.w, b1.x, b1.y, b1.z, b1.w};
#pragma unroll
        for (int c = 0; c < 8; c++) {
            acc[0][c] += a0 * bb[c];
            acc[1][c] += a1 * bb[c];
            acc[2][c] += a2 * bb[c];
            acc[3][c] += a3 * bb[c];
        }
    }

#pragma unroll
    for (int r = 0; r < 4; r++) {
        int gr = row0 + ty * 4 + r;
        if (gr < n_rows) {
            float4 v0 = make_float4(acc[r][0], acc[r][1], acc[r][2], acc[r][3]);
            float4 v1 = make_float4(acc[r][4], acc[r][5], acc[r][6], acc[r][7]);
            ((float4*)out)[gr * D4 + tx * 2 + 0] = v0;
            ((float4*)out)[gr * D4 + tx * 2 + 1] = v1;
        }
    }
}

// ---------------- el/er: per-node dot products ----------------
__global__ void el_er_kernel(const float* __restrict__ feat,
                             const float* __restrict__ al, const float* __restrict__ ar,
                             int n_nodes) {
    int w = (blockIdx.x * blockDim.x + threadIdx.x) >> 5;
    int lane = threadIdx.x & 31;
    if (w >= n_nodes) return;
    float4 f = ((const float4*)feat)[w * D4 + lane];
    float4 a = ((const float4*)al)[lane];
    float4 b = ((const float4*)ar)[lane];
    float sl = f.x * a.x + f.y * a.y + f.z * a.z + f.w * a.w;
    float sr = f.x * b.x + f.y * b.y + f.z * b.z + f.w * b.w;
#pragma unroll
    for (int o = 16; o > 0; o >>= 1) {
        sl += __shfl_xor_sync(0xffffffffu, sl, o);
        sr += __shfl_xor_sync(0xffffffffu, sr, o);
    }
    if (lane == 0) { g_el[w] = sl; g_er[w] = sr; }
}

// ---------------- edge softmax + aggregation: one warp per dst node ----------------
__global__ void aggregate_kernel(const float* __restrict__ feat,
                                 const float* __restrict__ bias,
                                 float* __restrict__ out, int n_nodes) {
    int w = (blockIdx.x * blockDim.x + threadIdx.x) >> 5;
    int lane = threadIdx.x & 31;
    if (w >= n_nodes) return;
    int start = g_offsets[w];
    int end = g_offsets[w + 1];
    float erd = g_er[w];

    // pass A: per-dst max of leaky_relu(el[src] + er[dst])
    float m = -1e30f;
    for (int i = start + lane; i < end; i += 32) {
        int s = g_esrc[i];
        float e = g_el[s] + erd;
        e = e > 0.f ? e : NEG_SLOPE * e;
        m = fmaxf(m, e);
    }
#pragma unroll
    for (int o = 16; o > 0; o >>= 1) m = fmaxf(m, __shfl_xor_sync(0xffffffffu, m, o));

    // pass B: exp, denominator, weighted feature accumulation
    float4 acc = make_float4(0.f, 0.f, 0.f, 0.f);
    float ssum = 0.f;
    const float4* feat4 = (const float4*)feat;
    for (int base = start; base < end; base += 32) {
        int i = base + lane;
        float ex = 0.f;
        int s = 0;
        if (i < end) {
            s = g_esrc[i];
            float e = g_el[s] + erd;
            e = e > 0.f ? e : NEG_SLOPE * e;
            ex = __expf(e - m);
        }
        ssum += ex;
        int cnt = end - base; if (cnt > 32) cnt = 32;
        for (int j = 0; j < cnt; j++) {
            float exj = __shfl_sync(0xffffffffu, ex, j);
            int   sj  = __shfl_sync(0xffffffffu, s, j);
            float4 f = feat4[sj * D4 + lane];
            acc.x += exj * f.x;
            acc.y += exj * f.y;
            acc.z += exj * f.z;
            acc.w += exj * f.w;
        }
    }
#pragma unroll
    for (int o = 16; o > 0; o >>= 1) ssum += __shfl_xor_sync(0xffffffffu, ssum, o);

    float4 b = ((const float4*)bias)[lane];
    float4 o4;
    if (end > start) {
        float inv = 1.0f / ssum;
        o4.x = fmaxf(acc.x * inv + b.x, 0.f);
        o4.y = fmaxf(acc.y * inv + b.y, 0.f);
        o4.z = fmaxf(acc.z * inv + b.z, 0.f);
        o4.w = fmaxf(acc.w * inv + b.w, 0.f);
    } else {
        o4.x = fmaxf(b.x, 0.f);
        o4.y = fmaxf(b.y, 0.f);
        o4.z = fmaxf(b.z, 0.f);
        o4.w = fmaxf(b.w, 0.f);
    }
    ((float4*)out)[w * D4 + lane] = o4;
}

// ---------------- pooling: graph_id is sorted, running per-block accumulate ----------------
__global__ void pool_kernel(const float* __restrict__ x, const int* __restrict__ gid,
                            int n_nodes) {
    int t = threadIdx.x;          // 0..127, one feature column each
    int n0 = blockIdx.x * 256;
    float acc = 0.f;
    int cur = -1;
    for (int i = 0; i < 256; i++) {
        int n = n0 + i;
        if (n >= n_nodes) break;
        int g = gid[n];
        if (g != cur) {
            if (cur >= 0) atomicAdd(&g_hg[cur * D + t], acc);
            acc = 0.f;
            cur = g;
        }
        acc += x[n * D + t];
    }
    if (cur >= 0) atomicAdd(&g_hg[cur * D + t], acc);
}

__global__ void gcnt_kernel(const int* __restrict__ gid, int n_nodes) {
    int g = threadIdx.x;
    if (g >= NG) return;
    // lower_bound for g and g+1 in sorted gid
    int lo = 0, hi = n_nodes;
    while (lo < hi) { int mid = (lo + hi) >> 1; if (gid[mid] < g) lo = mid + 1; else hi = mid; }
    int lb0 = lo;
    lo = 0; hi = n_nodes;
    while (lo < hi) { int mid = (lo + hi) >> 1; if (gid[mid] < g + 1) lo = mid + 1; else hi = mid; }
    g_gcnt[g] = lo - lb0;
}

// ---------------- final FC + log_softmax ----------------
__global__ void final_kernel(const float* __restrict__ Wfc, const float* __restrict__ bfc,
                             float* __restrict__ out) {
    int g = threadIdx.x;
    if (g >= NG) return;
    float cnt = (float)g_gcnt[g];
    if (cnt < 1.f) cnt = 1.f;
    float inv = 1.0f / cnt;
    float l0 = bfc[0], l1 = bfc[1];
    for (int k = 0; k < D; k++) {
        float v = g_hg[g * D + k] * inv;
        l0 += v * Wfc[k * 2 + 0];
        l1 += v * Wfc[k * 2 + 1];
    }
    float mx = fmaxf(l0, l1);
    float lse = mx + logf(expf(l0 - mx) + expf(l1 - mx));
    out[g * 2 + 0] = l0 - lse;
    out[g * 2 + 1] = l1 - lse;
}

// ---------------- launch ----------------
extern "C" void kernel_launch(void* const* d_in, const int* in_sizes, int n_in,
                              void* d_out, int out_size) {
    const float* h   = (const float*)d_in[0];
    const int*   src = (const int*)d_in[1];
    const int*   dst = (const int*)d_in[2];
    const int*   gid = (const int*)d_in[3];
    const float* W1  = (const float*)d_in[4];
    const float* al1 = (const float*)d_in[5];
    const float* ar1 = (const float*)d_in[6];
    const float* b1  = (const float*)d_in[7];
    const float* W2  = (const float*)d_in[8];
    const float* al2 = (const float*)d_in[9];
    const float* ar2 = (const float*)d_in[10];
    const float* b2  = (const float*)d_in[11];
    const float* Wfc = (const float*)d_in[12];
    const float* bfc = (const float*)d_in[13];
    float* out = (float*)d_out;

    int n_nodes = in_sizes[3];
    int E = in_sizes[1];
    if (n_nodes > NMAX) n_nodes = NMAX;
    if (E > EMAX) E = EMAX;

    static bool attr_done = false;
    if (!attr_done) {
        cudaFuncSetAttribute(gemm_kernel, cudaFuncAttributeMaxDynamicSharedMemorySize,
                             (D * D + 64 * D) * sizeof(float));
        attr_done = true;
    }
    size_t gemm_smem = (size_t)(D * D + 64 * D) * sizeof(float);

    int nblk_zero = 256;
    zero_kernel<<<nblk_zero, 256>>>(n_nodes);
    hist_kernel<<<512, 256>>>(dst, E);
    scan_kernel<<<1, 1024>>>(n_nodes);
    scatter_kernel<<<512, 256>>>(src, dst, E);

    int gemm_grid = (n_nodes + 63) / 64;
    int eler_grid = (n_nodes * 32 + 255) / 256;
    int agg_grid  = (n_nodes + 7) / 8;

    // layer 1
    gemm_kernel<<<gemm_grid, 256, gemm_smem>>>(h, W1, g_feat, n_nodes);
    el_er_kernel<<<eler_grid, 256>>>(g_feat, al1, ar1, n_nodes);
    aggregate_kernel<<<agg_grid, 256>>>(g_feat, b1, g_x, n_nodes);

    // layer 2
    gemm_kernel<<<gemm_grid, 256, gemm_smem>>>(g_x, W2, g_feat, n_nodes);
    el_er_kernel<<<eler_grid, 256>>>(g_feat, al2, ar2, n_nodes);
    aggregate_kernel<<<agg_grid, 256>>>(g_feat, b2, g_x, n_nodes);

    // pooling + classifier
    pool_kernel<<<(n_nodes + 255) / 256, 128>>>(g_x, gid, n_nodes);
    gcnt_kernel<<<1, 64>>>(gid, n_nodes);
    final_kernel<<<1, 64>>>(Wfc, bfc, out);
}